// round 13
// baseline (speedup 1.0000x reference)
#include <cuda_runtime.h>
#include <cuda_bf16.h>
#include <math.h>
#include <stdint.h>

// Problem constants
#define BATCH 2
#define SEQ   2048
#define HID   4096
#define NH    32
#define KVH   8
#define HD    128
#define NREP  (NH / KVH)          // 4
#define MROWS (BATCH * SEQ)       // 4096
#define KVDIM (KVH * HD)          // 1024

// ---------------------------------------------------------------------------
// Scratch (device globals; no runtime allocation allowed)
// ---------------------------------------------------------------------------
__device__ float g_q[(size_t)MROWS * NH * HD];      // 64 MB
__device__ float g_k[(size_t)MROWS * KVH * HD];     // 16 MB
__device__ float g_v[(size_t)MROWS * KVH * HD];     // 16 MB
__device__ float g_attn[(size_t)MROWS * HID];       // 64 MB
__device__ float g_cos[(size_t)MROWS * (HD / 2)];
__device__ float g_sin[(size_t)MROWS * (HD / 2)];

// ---------------------------------------------------------------------------
// RoPE cos/sin table. position = row % SEQ. fp64 trig.
// ---------------------------------------------------------------------------
__global__ void rope_table_kernel(float* __restrict__ cosT,
                                  float* __restrict__ sinT) {
    int bs = blockIdx.x;
    int d  = threadIdx.x;      // [0, 64)
    double p = (double)(bs % SEQ);
    double inv_freq = exp(-((double)(2 * d) / 128.0) * log(10000.0));
    double a = p * inv_freq;
    cosT[(size_t)bs * 64 + d] = (float)cos(a);
    sinT[(size_t)bs * 64 + d] = (float)sin(a);
}

// ---------------------------------------------------------------------------
// RoPE apply: x layout [B*S, heads, 128], in-place
// ---------------------------------------------------------------------------
__global__ void rope_apply_kernel(float* __restrict__ x,
                                  const float* __restrict__ cosT,
                                  const float* __restrict__ sinT,
                                  int heads) {
    long long i = (long long)blockIdx.x * blockDim.x + threadIdx.x;
    long long total = (long long)MROWS * heads * 64;
    if (i >= total) return;
    int d = (int)(i & 63);
    long long t = i >> 6;
    int h = (int)(t % heads);
    long long bs = t / heads;
    float c = cosT[bs * 64 + d];
    float s = sinT[bs * 64 + d];
    float* p = x + ((size_t)bs * heads + h) * HD;
    float x1 = p[d];
    float x2 = p[d + 64];
    p[d]      = x1 * c - x2 * s;
    p[d + 64] = x2 * c + x1 * s;
}

// ---------------------------------------------------------------------------
// tf32 helpers
// ---------------------------------------------------------------------------
__device__ __forceinline__ uint32_t f2tf32(float f) {
    uint32_t r;
    asm("cvt.rna.tf32.f32 %0, %1;" : "=r"(r) : "f"(f));
    return r;
}

__device__ __forceinline__ void split_tf32(float x, uint32_t& h, uint32_t& l) {
    uint32_t hh = f2tf32(x);
    h = hh;
    l = f2tf32(x - __uint_as_float(hh));
}

__device__ __forceinline__ void mma_tf32(float c[4], const uint32_t a[4],
                                         const uint32_t b[2]) {
    asm volatile(
        "mma.sync.aligned.m16n8k8.row.col.f32.tf32.tf32.f32 "
        "{%0,%1,%2,%3}, {%4,%5,%6,%7}, {%8,%9}, {%0,%1,%2,%3};"
        : "+f"(c[0]), "+f"(c[1]), "+f"(c[2]), "+f"(c[3])
        : "r"(a[0]), "r"(a[1]), "r"(a[2]), "r"(a[3]), "r"(b[0]), "r"(b[1]));
}

// ---------------------------------------------------------------------------
// Plain tf32 GEMM: C[M,N] = A[M,K] @ B[K,N], row-major.
// 128x128 CTA tile, BK=32, 256 threads (8 warps), warp tile 64x32.
// ---------------------------------------------------------------------------
#define AS_STRIDE 36    // 32 + 4  -> conflict-free A-fragment LDS
#define BS_STRIDE 136   // 128 + 8 -> conflict-free B-fragment LDS

__global__ __launch_bounds__(256)
void tgemm_kernel(const float* __restrict__ A, const float* __restrict__ B,
                  float* __restrict__ C, int M, int N, int K) {
    __shared__ uint32_t As[128 * AS_STRIDE];   // [m][k]
    __shared__ uint32_t Bs[32 * BS_STRIDE];    // [k][n]

    const int tid  = threadIdx.x;
    const int lane = tid & 31;
    const int warp = tid >> 5;
    const int wm0 = (warp & 1) * 64;
    const int wn0 = (warp >> 1) * 32;
    const int m0 = blockIdx.y * 128;
    const int n0 = blockIdx.x * 128;
    const int lq = lane >> 2;
    const int lr = lane & 3;

    float c[4][4][4];
#pragma unroll
    for (int mi = 0; mi < 4; mi++)
#pragma unroll
        for (int ni = 0; ni < 4; ni++)
#pragma unroll
            for (int r = 0; r < 4; r++) c[mi][ni][r] = 0.0f;

    for (int kt = 0; kt < K; kt += 32) {
#pragma unroll
        for (int l = 0; l < 4; l++) {
            int idx = tid + l * 256;
            int row = idx >> 3;
            int cc  = (idx & 7) * 4;
            float4 v = *(const float4*)(A + (size_t)(m0 + row) * K + kt + cc);
            uint32_t* p = &As[row * AS_STRIDE + cc];
            p[0] = f2tf32(v.x); p[1] = f2tf32(v.y);
            p[2] = f2tf32(v.z); p[3] = f2tf32(v.w);
        }
#pragma unroll
        for (int l = 0; l < 4; l++) {
            int idx = tid + l * 256;
            int row = idx >> 5;
            int cc  = (idx & 31) * 4;
            float4 v = *(const float4*)(B + (size_t)(kt + row) * N + n0 + cc);
            uint32_t* p = &Bs[row * BS_STRIDE + cc];
            p[0] = f2tf32(v.x); p[1] = f2tf32(v.y);
            p[2] = f2tf32(v.z); p[3] = f2tf32(v.w);
        }
        __syncthreads();

#pragma unroll
        for (int kk = 0; kk < 32; kk += 8) {
            uint32_t a[4][4], b[4][2];
#pragma unroll
            for (int mi = 0; mi < 4; mi++) {
                int rb = wm0 + mi * 16 + lq;
                a[mi][0] = As[rb * AS_STRIDE + kk + lr];
                a[mi][1] = As[(rb + 8) * AS_STRIDE + kk + lr];
                a[mi][2] = As[rb * AS_STRIDE + kk + lr + 4];
                a[mi][3] = As[(rb + 8) * AS_STRIDE + kk + lr + 4];
            }
#pragma unroll
            for (int ni = 0; ni < 4; ni++) {
                int cb = wn0 + ni * 8 + lq;
                b[ni][0] = Bs[(kk + lr) * BS_STRIDE + cb];
                b[ni][1] = Bs[(kk + lr + 4) * BS_STRIDE + cb];
            }
#pragma unroll
            for (int mi = 0; mi < 4; mi++)
#pragma unroll
                for (int ni = 0; ni < 4; ni++)
                    mma_tf32(c[mi][ni], a[mi], b[ni]);
        }
        __syncthreads();
    }

#pragma unroll
    for (int mi = 0; mi < 4; mi++) {
#pragma unroll
        for (int ni = 0; ni < 4; ni++) {
            int r   = m0 + wm0 + mi * 16 + lq;
            int col = n0 + wn0 + ni * 8 + lr * 2;
            *(float2*)(C + (size_t)r * N + col) =
                make_float2(c[mi][ni][0], c[mi][ni][1]);
            *(float2*)(C + (size_t)(r + 8) * N + col) =
                make_float2(c[mi][ni][2], c[mi][ni][3]);
        }
    }
}

// ---------------------------------------------------------------------------
// Flash attention, compensated-tf32 MMA, pipelined, 512 THREADS (16 warps).
// BM=128, BN=64, D=128. Grid (SEQ/128, NH, BATCH).
// Warp w: row group rw=(w&7)*16 (16 rows). S-phase: key-half cw=(w>>3)*32
// (16x32 S tile); softmax merged across warp pairs via one smem exchange of
// (pmax, psum). PV-phase: d-half dc=(w>>3)*64 (16x64 O tile).
// 4 warps/SMSP -> latency hiding; per-warp MMA chain halved vs 256-thr ver.
// Dynamic smem (floats):
//   Qs[128][132] 16896 | K hi/lo x2 bufs 4x2304 | Psh/Psl 2x8704
//   Vth/Vtl [128][36] 2x4608 | Pex 512  -> 53248 fl = 212992 B
// ---------------------------------------------------------------------------
#define ATTN_SMEM_BYTES 212992

__global__ __launch_bounds__(512)
void attn_mma_kernel(const float* __restrict__ Q, const float* __restrict__ K,
                     const float* __restrict__ V, float* __restrict__ O) {
    extern __shared__ float sm[];
    float* Qs  = sm;                 // [128][132] fp32 (scaled)
    float* Kh0 = Qs + 16896;         // [64][36] x2 bufs
    float* Kl0 = Kh0 + 2304;
    float* Kh1 = Kl0 + 2304;
    float* Kl1 = Kh1 + 2304;
    float* Psh = Kl1 + 2304;         // [128][68]
    float* Psl = Psh + 8704;
    float* Vth = Psl + 8704;         // [128][36] (d-major)
    float* Vtl = Vth + 4608;
    float2* Pex = (float2*)(Vtl + 4608);  // [2][128] (pmax, psum)

    float* KhB[2] = {Kh0, Kh1};
    float* KlB[2] = {Kl0, Kl1};

    const int qi  = gridDim.x - 1 - blockIdx.x;   // longest CTAs first
    const int q0g = qi * 128;
    const int h   = blockIdx.y;
    const int b   = blockIdx.z;
    const int kvh = h / NREP;
    const float* Qb = Q + ((size_t)b * SEQ * NH + h) * HD;
    const float* Kb = K + ((size_t)b * SEQ * KVH + kvh) * HD;
    const float* Vb = V + ((size_t)b * SEQ * KVH + kvh) * HD;
    float* Ob = O + (size_t)b * SEQ * HID + (size_t)h * HD;

    const int tid  = threadIdx.x;
    const int lane = tid & 31;
    const int warp = tid >> 5;
    const int wm   = (warp & 7) * 16;     // row group
    const int cw   = warp >> 3;           // 0/1: key-half (S) / d-half (PV)
    const int ch   = cw * 32;             // S key offset
    const int dc   = cw * 64;             // PV d offset
    const int lq   = lane >> 2;
    const int lr   = lane & 3;
    const float scale = 0.08838834764831845f;  // 1/sqrt(128)

    // K-chunk load: 64x32 floats, 1 float4/thread
    const int krow = tid >> 3;            // 0..63
    const int kcol = (tid & 7) * 4;

    // V load: thread owns column dcol, 8 j-rows
    const int dcol = tid & 127;
    const int jh   = (tid >> 7) * 8;      // 0,8,16,24

    // ---- load Q tile once (scaled fp32) ----
#pragma unroll
    for (int l = 0; l < 8; l++) {
        int idx = tid + l * 512;
        int row = idx >> 5;
        int c4  = (idx & 31) * 4;
        float4 v = *(const float4*)(Qb + (size_t)(q0g + row) * (NH * HD) + c4);
        float* p = Qs + row * 132 + c4;
        p[0] = v.x * scale; p[1] = v.y * scale;
        p[2] = v.z * scale; p[3] = v.w * scale;
    }

    float oc[8][4];
#pragma unroll
    for (int nt = 0; nt < 8; nt++)
#pragma unroll
        for (int r = 0; r < 4; r++) oc[nt][r] = 0.0f;
    float m_i[2] = {-1e30f, -1e30f};
    float l_i[2] = {0.0f, 0.0f};

    const int jmax = q0g + 64;
    for (int j0 = 0; j0 <= jmax; j0 += 64) {
        const float* Kt  = Kb + (size_t)j0 * KVDIM;
        const float* Vt0 = Vb + (size_t)j0 * KVDIM;

        // ================== S = Qscaled @ K^T (pipelined K chunks) ========
        float sc[4][4];
#pragma unroll
        for (int nt = 0; nt < 4; nt++)
#pragma unroll
            for (int r = 0; r < 4; r++) sc[nt][r] = 0.0f;

        float4 kr = *(const float4*)(Kt + (size_t)krow * KVDIM + kcol);

#pragma unroll
        for (int kc = 0; kc < 4; kc++) {
            float* ph = KhB[kc & 1];
            float* pl = KlB[kc & 1];
            {
                uint32_t hh, ll;
                float* p0h = ph + krow * 36 + kcol;
                float* p0l = pl + krow * 36 + kcol;
                split_tf32(kr.x, hh, ll); p0h[0] = __uint_as_float(hh); p0l[0] = __uint_as_float(ll);
                split_tf32(kr.y, hh, ll); p0h[1] = __uint_as_float(hh); p0l[1] = __uint_as_float(ll);
                split_tf32(kr.z, hh, ll); p0h[2] = __uint_as_float(hh); p0l[2] = __uint_as_float(ll);
                split_tf32(kr.w, hh, ll); p0h[3] = __uint_as_float(hh); p0l[3] = __uint_as_float(ll);
            }
            __syncthreads();
            if (kc < 3)
                kr = *(const float4*)(Kt + (size_t)krow * KVDIM + (kc + 1) * 32 + kcol);
#pragma unroll
            for (int ks = 0; ks < 4; ks++) {
                int kq = kc * 32 + ks * 8;
                const float* q0p = Qs + (wm + lq) * 132 + kq + lr;
                const float* q1p = Qs + (wm + lq + 8) * 132 + kq + lr;
                uint32_t ah[4], al[4];
                split_tf32(q0p[0], ah[0], al[0]);
                split_tf32(q1p[0], ah[1], al[1]);
                split_tf32(q0p[4], ah[2], al[2]);
                split_tf32(q1p[4], ah[3], al[3]);
#pragma unroll
                for (int nt = 0; nt < 4; nt++) {
                    int boff = (ch + nt * 8 + lq) * 36 + ks * 8 + lr;
                    uint32_t bh[2] = {__float_as_uint(ph[boff]),
                                      __float_as_uint(ph[boff + 4])};
                    uint32_t bl[2] = {__float_as_uint(pl[boff]),
                                      __float_as_uint(pl[boff + 4])};
                    mma_tf32(sc[nt], ah, bh);
                    mma_tf32(sc[nt], al, bh);
                    mma_tf32(sc[nt], ah, bl);
                }
            }
        }

        // prefetch V chunk 0 (rows j0..j0+31), hidden under softmax
        float vreg[8];
#pragma unroll
        for (int jj = 0; jj < 8; jj++)
            vreg[jj] = Vt0[(size_t)(jh + jj) * KVDIM + dcol];

        // ================== causal mask (diagonal region only) ============
        if (j0 + 64 > q0g) {
            int rg0 = q0g + wm + lq;
            int rg1 = rg0 + 8;
#pragma unroll
            for (int nt = 0; nt < 4; nt++) {
                int cg = j0 + ch + nt * 8 + lr * 2;
                if (cg     > rg0) sc[nt][0] = -1e30f;
                if (cg + 1 > rg0) sc[nt][1] = -1e30f;
                if (cg     > rg1) sc[nt][2] = -1e30f;
                if (cg + 1 > rg1) sc[nt][3] = -1e30f;
            }
        }

        // ================== softmax part 1: per-half partials =============
        float pm0 = -1e30f, pm1 = -1e30f;
#pragma unroll
        for (int nt = 0; nt < 4; nt++) {
            pm0 = fmaxf(pm0, fmaxf(sc[nt][0], sc[nt][1]));
            pm1 = fmaxf(pm1, fmaxf(sc[nt][2], sc[nt][3]));
        }
        pm0 = fmaxf(pm0, __shfl_xor_sync(0xffffffffu, pm0, 1));
        pm0 = fmaxf(pm0, __shfl_xor_sync(0xffffffffu, pm0, 2));
        pm1 = fmaxf(pm1, __shfl_xor_sync(0xffffffffu, pm1, 1));
        pm1 = fmaxf(pm1, __shfl_xor_sync(0xffffffffu, pm1, 2));
        float ps0 = 0.0f, ps1 = 0.0f;
#pragma unroll
        for (int nt = 0; nt < 4; nt++) {
            sc[nt][0] = __expf(sc[nt][0] - pm0);
            sc[nt][1] = __expf(sc[nt][1] - pm0);
            sc[nt][2] = __expf(sc[nt][2] - pm1);
            sc[nt][3] = __expf(sc[nt][3] - pm1);
            ps0 += sc[nt][0] + sc[nt][1];
            ps1 += sc[nt][2] + sc[nt][3];
        }
        ps0 += __shfl_xor_sync(0xffffffffu, ps0, 1);
        ps0 += __shfl_xor_sync(0xffffffffu, ps0, 2);
        ps1 += __shfl_xor_sync(0xffffffffu, ps1, 1);
        ps1 += __shfl_xor_sync(0xffffffffu, ps1, 2);
        if (lr == 0) {
            Pex[cw * 128 + wm + lq]     = make_float2(pm0, ps0);
            Pex[cw * 128 + wm + lq + 8] = make_float2(pm1, ps1);
        }
        __syncthreads();

        // ================== softmax part 2: merge halves ==================
        float2 o0 = Pex[(1 - cw) * 128 + wm + lq];
        float2 o1 = Pex[(1 - cw) * 128 + wm + lq + 8];
        float mn0 = fmaxf(m_i[0], fmaxf(pm0, o0.x));
        float mn1 = fmaxf(m_i[1], fmaxf(pm1, o1.x));
        float f0  = __expf(pm0 - mn0), fo0 = __expf(o0.x - mn0);
        float f1  = __expf(pm1 - mn1), fo1 = __expf(o1.x - mn1);
        float al0 = __expf(m_i[0] - mn0), al1 = __expf(m_i[1] - mn1);
        l_i[0] = l_i[0] * al0 + ps0 * f0 + o0.y * fo0;  m_i[0] = mn0;
        l_i[1] = l_i[1] * al1 + ps1 * f1 + o1.y * fo1;  m_i[1] = mn1;
#pragma unroll
        for (int nt = 0; nt < 8; nt++) {
            oc[nt][0] *= al0; oc[nt][1] *= al0;
            oc[nt][2] *= al1; oc[nt][3] *= al1;
        }

        // ================== write P (hi/lo, scaled to global max) =========
        {
            int r0 = wm + lq, r1 = r0 + 8;
#pragma unroll
            for (int nt = 0; nt < 4; nt++) {
                int c = ch + nt * 8 + lr * 2;
                uint32_t h0, l0, h1, l1;
                split_tf32(sc[nt][0] * f0, h0, l0);
                split_tf32(sc[nt][1] * f0, h1, l1);
                *(float2*)(Psh + r0 * 68 + c) =
                    make_float2(__uint_as_float(h0), __uint_as_float(h1));
                *(float2*)(Psl + r0 * 68 + c) =
                    make_float2(__uint_as_float(l0), __uint_as_float(l1));
                split_tf32(sc[nt][2] * f1, h0, l0);
                split_tf32(sc[nt][3] * f1, h1, l1);
                *(float2*)(Psh + r1 * 68 + c) =
                    make_float2(__uint_as_float(h0), __uint_as_float(h1));
                *(float2*)(Psl + r1 * 68 + c) =
                    make_float2(__uint_as_float(l0), __uint_as_float(l1));
            }
        }

        // ================== O += P @ V  (pipelined V chunks) ==============
#pragma unroll
        for (int jc = 0; jc < 2; jc++) {
            __syncthreads();   // Vt readers done (prev chunk/tile); P visible
#pragma unroll
            for (int jj = 0; jj < 8; jj++) {
                uint32_t hh, ll;
                split_tf32(vreg[jj], hh, ll);
                Vth[dcol * 36 + jh + jj] = __uint_as_float(hh);
                Vtl[dcol * 36 + jh + jj] = __uint_as_float(ll);
            }
            __syncthreads();
            if (jc == 0) {
#pragma unroll
                for (int jj = 0; jj < 8; jj++)
                    vreg[jj] = Vt0[(size_t)(32 + jh + jj) * KVDIM + dcol];
            }
#pragma unroll
            for (int ks = 0; ks < 4; ks++) {
                int kp = jc * 32 + ks * 8;
                int a0 = (wm + lq) * 68 + kp + lr;
                int a1 = (wm + lq + 8) * 68 + kp + lr;
                uint32_t ah[4] = {__float_as_uint(Psh[a0]), __float_as_uint(Psh[a1]),
                                  __float_as_uint(Psh[a0 + 4]), __float_as_uint(Psh[a1 + 4])};
                uint32_t al[4] = {__float_as_uint(Psl[a0]), __float_as_uint(Psl[a1]),
                                  __float_as_uint(Psl[a0 + 4]), __float_as_uint(Psl[a1 + 4])};
#pragma unroll
                for (int nt = 0; nt < 8; nt++) {
                    int boff = (dc + nt * 8 + lq) * 36 + ks * 8 + lr;
                    uint32_t bh[2] = {__float_as_uint(Vth[boff]),
                                      __float_as_uint(Vth[boff + 4])};
                    uint32_t bl[2] = {__float_as_uint(Vtl[boff]),
                                      __float_as_uint(Vtl[boff + 4])};
                    mma_tf32(oc[nt], ah, bh);
                    mma_tf32(oc[nt], al, bh);
                    mma_tf32(oc[nt], ah, bl);
                }
            }
        }
        __syncthreads();   // all smem readers done before next tile's writes
    }

    // ================== epilogue: normalize + store =======================
    float inv0 = 1.0f / l_i[0], inv1 = 1.0f / l_i[1];
    int r0 = q0g + wm + lq;
#pragma unroll
    for (int nt = 0; nt < 8; nt++) {
        int c = dc + nt * 8 + lr * 2;
        *(float2*)(Ob + (size_t)r0 * HID + c) =
            make_float2(oc[nt][0] * inv0, oc[nt][1] * inv0);
        *(float2*)(Ob + (size_t)(r0 + 8) * HID + c) =
            make_float2(oc[nt][2] * inv1, oc[nt][3] * inv1);
    }
}

// ---------------------------------------------------------------------------
// Launch
// ---------------------------------------------------------------------------
extern "C" void kernel_launch(void* const* d_in, const int* in_sizes, int n_in,
                              void* d_out, int out_size) {
    const float* hidden = (const float*)d_in[0];
    const float* wq = (const float*)d_in[2];
    const float* wk = (const float*)d_in[3];
    const float* wv = (const float*)d_in[4];
    const float* wo = (const float*)d_in[5];
    float*       out = (float*)d_out;

    float *q, *k, *v, *attn, *cosT, *sinT;
    cudaGetSymbolAddress((void**)&q,    g_q);
    cudaGetSymbolAddress((void**)&k,    g_k);
    cudaGetSymbolAddress((void**)&v,    g_v);
    cudaGetSymbolAddress((void**)&attn, g_attn);
    cudaGetSymbolAddress((void**)&cosT, g_cos);
    cudaGetSymbolAddress((void**)&sinT, g_sin);

    cudaFuncSetAttribute(attn_mma_kernel,
                         cudaFuncAttributeMaxDynamicSharedMemorySize,
                         ATTN_SMEM_BYTES);

    // 1. RoPE table
    rope_table_kernel<<<MROWS, 64>>>(cosT, sinT);

    // 2. QKV projections (plain tf32 tensor cores)
    tgemm_kernel<<<dim3(HID / 128, MROWS / 128), 256>>>(hidden, wq, q, MROWS, HID, HID);
    tgemm_kernel<<<dim3(KVDIM / 128, MROWS / 128), 256>>>(hidden, wk, k, MROWS, KVDIM, HID);
    tgemm_kernel<<<dim3(KVDIM / 128, MROWS / 128), 256>>>(hidden, wv, v, MROWS, KVDIM, HID);

    // 3. RoPE apply (Q, then K)
    {
        long long tq = (long long)MROWS * NH * 64;
        rope_apply_kernel<<<(unsigned)((tq + 255) / 256), 256>>>(q, cosT, sinT, NH);
        long long tk = (long long)MROWS * KVH * 64;
        rope_apply_kernel<<<(unsigned)((tk + 255) / 256), 256>>>(k, cosT, sinT, KVH);
    }

    // 4. Attention (512-thread pipelined compensated tf32 MMA)
    attn_mma_kernel<<<dim3(SEQ / 128, NH, BATCH), 512, ATTN_SMEM_BYTES>>>(q, k, v, attn);

    // 5. Output projection (plain tf32 tensor cores)
    tgemm_kernel<<<dim3(HID / 128, MROWS / 128), 256>>>(attn, wo, out, MROWS, HID, HID);
}